// round 10
// baseline (speedup 1.0000x reference)
#include <cuda_runtime.h>
#include <cuda_fp16.h>
#include <cstdint>

#define M_BATCH 8192
#define N_OUT   4096
#define K_IN    4096

// Scratch (device globals: allocation-free per harness rules)
__device__ __half g_Wh[(size_t)N_OUT * K_IN];    // fp16 sampled weights (n,k)
__device__ __half g_Xh[(size_t)M_BATCH * K_IN];  // fp16 copy of x
__device__ float  g_bias[N_OUT];                 // sampled bias column
__device__ float  g_klpart[8320];                // per-block KL partials

#define WBLK     8194                             // 16,781,312 elems / (256 thr * 8)
#define XBLK     16384                            // (8192*4096/8)/256
#define PREP_GRID (WBLK + XBLK)

// ---------------------------------------------------------------------------
// Fused prep: blocks [0,WBLK) sample W -> fp16 + bias + KL partials
//             (8 elements per thread, exact fit, no bounds checks),
//             blocks [WBLK, WBLK+XBLK) convert X -> fp16.
// ---------------------------------------------------------------------------
__global__ __launch_bounds__(256) void prep_fused(const float* __restrict__ qmu,
                                                  const float* __restrict__ qls,
                                                  const float* __restrict__ pmu,
                                                  const float* __restrict__ eps,
                                                  const float* __restrict__ plsp,
                                                  const float* __restrict__ X) {
    const int b = blockIdx.x;
    if (b < WBLK) {
        const float pls  = *plsp;
        const float inv2 = 0.5f * __expf(-2.0f * pls);
        const int i8 = b * 256 + threadIdx.x;        // thread handles elems 8*i8..+7
        // 8 independent 16B loads per array pair (front-batched for MLP)
        float4 qm0 = ((const float4*)qmu)[2 * i8];
        float4 qm1 = ((const float4*)qmu)[2 * i8 + 1];
        float4 ql0 = ((const float4*)qls)[2 * i8];
        float4 ql1 = ((const float4*)qls)[2 * i8 + 1];
        float4 pm0 = ((const float4*)pmu)[2 * i8];
        float4 pm1 = ((const float4*)pmu)[2 * i8 + 1];
        float4 ep0 = ((const float4*)eps)[2 * i8];
        float4 ep1 = ((const float4*)eps)[2 * i8 + 1];
        const float* qmv = &qm0.x;   // [8] contiguous (two float4s back-to-back)
        const float* qlv = &ql0.x;
        const float* pmv = &pm0.x;
        const float* epv = &ep0.x;
        (void)qm1; (void)ql1; (void)pm1; (void)ep1;

        const int e0 = i8 * 8;
        int n = e0 / 4097;                           // one div per 8 elements
        int k = e0 - n * 4097;
        float kl = 0.f;
        #pragma unroll
        for (int j = 0; j < 8; j++) {
            float qmj = (j < 4 ? (&qm0.x)[j] : (&qm1.x)[j - 4]);
            float qlj = (j < 4 ? (&ql0.x)[j] : (&ql1.x)[j - 4]);
            float pmj = (j < 4 ? (&pm0.x)[j] : (&pm1.x)[j - 4]);
            float epj = (j < 4 ? (&ep0.x)[j] : (&ep1.x)[j - 4]);
            float qs = __expf(qlj);
            float w  = fmaf(qs, epj, qmj);
            if (k < K_IN) g_Wh[(size_t)n * K_IN + k] = __float2half_rn(w);
            else          g_bias[n] = w;
            float d = pmj - qmj;
            kl += (pls - qlj) + fmaf(qs, qs, d * d) * inv2 - 0.5f;
            if (++k == 4097) { k = 0; n++; }
        }
        (void)qmv; (void)qlv; (void)pmv; (void)epv;

        __shared__ float red[256];
        red[threadIdx.x] = kl;
        __syncthreads();
        #pragma unroll
        for (int s = 128; s > 0; s >>= 1) {
            if (threadIdx.x < s) red[threadIdx.x] += red[threadIdx.x + s];
            __syncthreads();
        }
        if (threadIdx.x == 0) g_klpart[b] = red[0];
    } else {
        const int i = (b - WBLK) * 256 + threadIdx.x;   // < 4,194,304
        float4 a = ((const float4*)X)[2 * i];
        float4 c = ((const float4*)X)[2 * i + 1];
        __half2 h[4];
        h[0] = __floats2half2_rn(a.x, a.y);
        h[1] = __floats2half2_rn(a.z, a.w);
        h[2] = __floats2half2_rn(c.x, c.y);
        h[3] = __floats2half2_rn(c.z, c.w);
        ((uint4*)g_Xh)[i] = *(uint4*)h;
    }
}

__global__ void kl_reduce_kernel(float* __restrict__ out, long long idx) {
    float local = 0.f;
    for (int i = threadIdx.x; i < WBLK; i += 256) local += g_klpart[i];
    __shared__ float red[256];
    red[threadIdx.x] = local;
    __syncthreads();
    #pragma unroll
    for (int s = 128; s > 0; s >>= 1) {
        if (threadIdx.x < s) red[threadIdx.x] += red[threadIdx.x + s];
        __syncthreads();
    }
    if (threadIdx.x == 0) out[idx] = red[0];
}

// ---------------------------------------------------------------------------
// fp16 mma.sync GEMM: out[m][n] = sum_k X[m][k]*W[n][k] + bias[n]
// CTA 128x128x64(halfs), 8 warps (2Mx4N), warp tile 64x32, 2 CTAs/SM.
// ldmatrix.x4.b16 on XOR-swizzled 128B rows, m16n8k16.f16, f32 acc.
// 3-stage cp.async pipeline (96 KB smem/CTA). Round-6 mainloop, frozen.
// ---------------------------------------------------------------------------
#define BM 128
#define BN 128
#define BK 64                          // halfs = 128 bytes per row
#define A_BYTES (BM * 128)             // 16384
#define STG_BYTES ((BM + BN) * 128)    // 32768
#define SMEM_TOTAL (3 * STG_BYTES)

__device__ __forceinline__ void cpa16(uint32_t daddr, const void* src) {
    asm volatile("cp.async.cg.shared.global [%0], [%1], 16;" :: "r"(daddr), "l"(src));
}

__device__ __forceinline__ void ldsm4(uint32_t* r, uint32_t addr) {
    asm volatile("ldmatrix.sync.aligned.m8n8.x4.shared.b16 {%0,%1,%2,%3}, [%4];"
                 : "=r"(r[0]), "=r"(r[1]), "=r"(r[2]), "=r"(r[3]) : "r"(addr));
}

__device__ __forceinline__ void mma16(float* c, const uint32_t* a, uint32_t b0, uint32_t b1) {
    asm volatile(
        "mma.sync.aligned.m16n8k16.row.col.f32.f16.f16.f32 "
        "{%0,%1,%2,%3}, {%4,%5,%6,%7}, {%8,%9}, {%0,%1,%2,%3};\n"
        : "+f"(c[0]), "+f"(c[1]), "+f"(c[2]), "+f"(c[3])
        : "r"(a[0]), "r"(a[1]), "r"(a[2]), "r"(a[3]), "r"(b0), "r"(b1));
}

__global__ __launch_bounds__(256, 2) void gemm_kernel(float* __restrict__ out) {
    extern __shared__ char smem[];
    uint32_t sbase;
    asm("{ .reg .u64 t; cvta.to.shared.u64 t, %1; cvt.u32.u64 %0, t; }"
        : "=r"(sbase) : "l"(smem));
    const int tid  = threadIdx.x;
    const int wid  = tid >> 5;
    const int lane = tid & 31;

    // GROUP_M=16 schedule: 64 M-tiles x 32 N-tiles
    const int pid   = blockIdx.x;
    const int group = pid >> 9;                       // / (16*32)
    const int rem   = pid & 511;
    const int blockM = ((group << 4) + (rem & 15)) * BM;
    const int blockN = (rem >> 4) * BN;

    // ---- loader mapping: q = 16B chunk (8 halfs), rows strided by 32 ----
    const int q  = tid & 7;
    const int r0 = tid >> 3;                          // 0..31
    const __half* gA = g_Xh + (size_t)(blockM + r0) * K_IN + q * 8;
    const __half* gB = g_Wh + (size_t)(blockN + r0) * K_IN + q * 8;
    const uint32_t soA = r0 * 128 + ((q ^ (r0 & 7)) << 4);
    const uint32_t soB = A_BYTES + soA;

    // ---- fragment geometry ----
    const int mBase = (wid & 1) * 64;                 // 2 M-warps
    const int nBase = (wid >> 1) * 32;                // 4 N-warps x 32
    const uint32_t rl = lane & 7;
    const uint32_t aKbAdd = (lane >> 4) & 1;
    const uint32_t bKbAdd = (lane >> 3) & 1;
    uint32_t aRowOff[4], bRowOff[2];
    #pragma unroll
    for (int i = 0; i < 4; i++)
        aRowOff[i] = (mBase + i * 16 + (lane & 7) + 8 * ((lane >> 3) & 1)) * 128;
    #pragma unroll
    for (int j2 = 0; j2 < 2; j2++)
        bRowOff[j2] = A_BYTES + (nBase + j2 * 16 + (lane & 7) + 8 * ((lane >> 4) & 1)) * 128;

    float acc[4][4][4];
    #pragma unroll
    for (int i = 0; i < 4; i++)
        #pragma unroll
        for (int j = 0; j < 4; j++)
            #pragma unroll
            for (int r = 0; r < 4; r++) acc[i][j][r] = 0.f;

    const int KT = K_IN / BK;                          // 64

    // prologue: stages 0,1
    #pragma unroll
    for (int t = 0; t < 2; t++) {
        uint32_t base = sbase + t * STG_BYTES;
        #pragma unroll
        for (int i = 0; i < 4; i++) {
            cpa16(base + soA + i * 4096, gA + (size_t)t * BK + (size_t)i * 32 * K_IN);
            cpa16(base + soB + i * 4096, gB + (size_t)t * BK + (size_t)i * 32 * K_IN);
        }
        asm volatile("cp.async.commit_group;");
    }

    int sCur = 0, sNxt = 2;                            // buf indices mod 3
    for (int t = 0; t < KT; t++) {
        asm volatile("cp.async.wait_group 1;");
        __syncthreads();

        if (t + 2 < KT) {
            uint32_t base = sbase + sNxt * STG_BYTES;
            const __half* ga = gA + (size_t)(t + 2) * BK;
            const __half* gb = gB + (size_t)(t + 2) * BK;
            #pragma unroll
            for (int i = 0; i < 4; i++) {
                cpa16(base + soA + i * 4096, ga + (size_t)i * 32 * K_IN);
                cpa16(base + soB + i * 4096, gb + (size_t)i * 32 * K_IN);
            }
        }
        asm volatile("cp.async.commit_group;");

        const uint32_t stage = sbase + sCur * STG_BYTES;
        #pragma unroll
        for (int c = 0; c < 4; c++) {                  // 4 x k16 = BK
            const uint32_t aXor = ((2 * c + aKbAdd) ^ rl) << 4;
            const uint32_t bXor = ((2 * c + bKbAdd) ^ rl) << 4;
            uint32_t af[4][4], bq[2][4];
            #pragma unroll
            for (int i = 0; i < 4; i++) ldsm4(af[i], stage + aRowOff[i] + aXor);
            #pragma unroll
            for (int j2 = 0; j2 < 2; j2++) ldsm4(bq[j2], stage + bRowOff[j2] + bXor);
            #pragma unroll
            for (int i = 0; i < 4; i++)
                #pragma unroll
                for (int j2 = 0; j2 < 2; j2++) {
                    mma16(acc[i][2 * j2],     af[i], bq[j2][0], bq[j2][1]);
                    mma16(acc[i][2 * j2 + 1], af[i], bq[j2][2], bq[j2][3]);
                }
        }
        sCur = sCur == 2 ? 0 : sCur + 1;
        sNxt = sNxt == 2 ? 0 : sNxt + 1;
    }

    // ---- epilogue: bias add + fp32 stores ----
    const int ly = lane >> 2, lx = lane & 3;
    float2 bias2[4];
    #pragma unroll
    for (int j = 0; j < 4; j++)
        bias2[j] = *(const float2*)&g_bias[blockN + nBase + j * 8 + lx * 2];
    #pragma unroll
    for (int i = 0; i < 4; i++) {
        const int row0 = blockM + mBase + i * 16 + ly;
        #pragma unroll
        for (int j = 0; j < 4; j++) {
            const int col = blockN + nBase + j * 8 + lx * 2;
            float2 v0 = make_float2(acc[i][j][0] + bias2[j].x, acc[i][j][1] + bias2[j].y);
            float2 v1 = make_float2(acc[i][j][2] + bias2[j].x, acc[i][j][3] + bias2[j].y);
            *(float2*)&out[(size_t)row0 * N_OUT + col] = v0;
            *(float2*)&out[(size_t)(row0 + 8) * N_OUT + col] = v1;
        }
    }
}

// ---------------------------------------------------------------------------
extern "C" void kernel_launch(void* const* d_in, const int* in_sizes, int n_in,
                              void* d_out, int out_size) {
    const float* x   = (const float*)d_in[0];
    const float* pls = (const float*)d_in[1];
    const float* qmu = (const float*)d_in[2];
    const float* qls = (const float*)d_in[3];
    const float* pmu = (const float*)d_in[4];
    const float* eps = (const float*)d_in[5];
    float* out = (float*)d_out;

    prep_fused<<<PREP_GRID, 256>>>(qmu, qls, pmu, eps, pls, x);

    cudaFuncSetAttribute(gemm_kernel, cudaFuncAttributeMaxDynamicSharedMemorySize, SMEM_TOTAL);
    gemm_kernel<<<(M_BATCH / BM) * (N_OUT / BN), 256, SMEM_TOTAL>>>(out);

    // KL reduce moved off the prep->gemm critical path (disjoint output region)
    kl_reduce_kernel<<<1, 256>>>(out, (long long)out_size - 1);
}

// round 11
// speedup vs baseline: 1.0313x; 1.0313x over previous
#include <cuda_runtime.h>
#include <cuda_fp16.h>
#include <cstdint>

#define M_BATCH 8192
#define N_OUT   4096
#define K_IN    4096

// Scratch (device globals: allocation-free per harness rules)
__device__ __half g_Wh[(size_t)N_OUT * K_IN];    // fp16 sampled weights (n,k)
__device__ __half g_Xh[(size_t)M_BATCH * K_IN];  // fp16 copy of x
__device__ float  g_bias[N_OUT];                 // sampled bias column
__device__ float  g_klpart[16640];               // per-block KL partials

#define NT4      4195328                          // (4096*4097)/4 float4s
#define WBLK     16388                            // ceil(NT4/256)
#define XBLK     16384                            // (8192*4096/8)/256
#define PREP_GRID (WBLK + XBLK)

// ---------------------------------------------------------------------------
// Fused prep: blocks [0,WBLK) sample W -> fp16 + bias + KL partials,
//             blocks [WBLK, WBLK+XBLK) convert X -> fp16. One pass, no loop.
// (round-9 version, measured 74 us @ 80% DRAM)
// ---------------------------------------------------------------------------
__global__ __launch_bounds__(256) void prep_fused(const float* __restrict__ qmu,
                                                  const float* __restrict__ qls,
                                                  const float* __restrict__ pmu,
                                                  const float* __restrict__ eps,
                                                  const float* __restrict__ plsp,
                                                  const float* __restrict__ X) {
    const int b = blockIdx.x;
    if (b < WBLK) {
        const float pls  = *plsp;
        const float inv2 = 0.5f * __expf(-2.0f * pls);
        float kl = 0.f;
        const int i4 = b * 256 + threadIdx.x;
        if (i4 < NT4) {
            float4 qm = ((const float4*)qmu)[i4];
            float4 ql = ((const float4*)qls)[i4];
            float4 pm = ((const float4*)pmu)[i4];
            float4 ep = ((const float4*)eps)[i4];
            #pragma unroll
            for (int j = 0; j < 4; j++) {
                float qmj = (&qm.x)[j], qlj = (&ql.x)[j];
                float pmj = (&pm.x)[j], epj = (&ep.x)[j];
                float qs = __expf(qlj);
                float w  = fmaf(qs, epj, qmj);
                int e = i4 * 4 + j;
                int n = e / 4097;
                int k = e - n * 4097;
                if (k < K_IN) g_Wh[(size_t)n * K_IN + k] = __float2half_rn(w);
                else          g_bias[n] = w;
                float d = pmj - qmj;
                kl += (pls - qlj) + fmaf(qs, qs, d * d) * inv2 - 0.5f;
            }
        }
        __shared__ float red[256];
        red[threadIdx.x] = kl;
        __syncthreads();
        #pragma unroll
        for (int s = 128; s > 0; s >>= 1) {
            if (threadIdx.x < s) red[threadIdx.x] += red[threadIdx.x + s];
            __syncthreads();
        }
        if (threadIdx.x == 0) g_klpart[b] = red[0];
    } else {
        const int i = (b - WBLK) * 256 + threadIdx.x;   // < 4,194,304
        float4 a = ((const float4*)X)[2 * i];
        float4 c = ((const float4*)X)[2 * i + 1];
        __half2 h[4];
        h[0] = __floats2half2_rn(a.x, a.y);
        h[1] = __floats2half2_rn(a.z, a.w);
        h[2] = __floats2half2_rn(c.x, c.y);
        h[3] = __floats2half2_rn(c.z, c.w);
        ((uint4*)g_Xh)[i] = *(uint4*)h;
    }
}

__global__ void kl_reduce_kernel(float* __restrict__ out, long long idx) {
    float local = 0.f;
    for (int i = threadIdx.x; i < WBLK; i += 256) local += g_klpart[i];
    __shared__ float red[256];
    red[threadIdx.x] = local;
    __syncthreads();
    #pragma unroll
    for (int s = 128; s > 0; s >>= 1) {
        if (threadIdx.x < s) red[threadIdx.x] += red[threadIdx.x + s];
        __syncthreads();
    }
    if (threadIdx.x == 0) out[idx] = red[0];
}

// ---------------------------------------------------------------------------
// fp16 mma.sync GEMM: out[m][n] = sum_k X[m][k]*W[n][k] + bias[n]
// CTA 128x128x64(halfs), 8 warps (2Mx4N), warp tile 64x32, 2 CTAs/SM.
// ldmatrix.x4.b16 on XOR-swizzled 128B rows, m16n8k16.f16, f32 acc.
// 3-stage cp.async pipeline (96 KB smem/CTA). Round-6 mainloop, frozen.
// ---------------------------------------------------------------------------
#define BM 128
#define BN 128
#define BK 64                          // halfs = 128 bytes per row
#define A_BYTES (BM * 128)             // 16384
#define STG_BYTES ((BM + BN) * 128)    // 32768
#define SMEM_TOTAL (3 * STG_BYTES)

__device__ __forceinline__ void cpa16(uint32_t daddr, const void* src) {
    asm volatile("cp.async.cg.shared.global [%0], [%1], 16;" :: "r"(daddr), "l"(src));
}

__device__ __forceinline__ void ldsm4(uint32_t* r, uint32_t addr) {
    asm volatile("ldmatrix.sync.aligned.m8n8.x4.shared.b16 {%0,%1,%2,%3}, [%4];"
                 : "=r"(r[0]), "=r"(r[1]), "=r"(r[2]), "=r"(r[3]) : "r"(addr));
}

__device__ __forceinline__ void mma16(float* c, const uint32_t* a, uint32_t b0, uint32_t b1) {
    asm volatile(
        "mma.sync.aligned.m16n8k16.row.col.f32.f16.f16.f32 "
        "{%0,%1,%2,%3}, {%4,%5,%6,%7}, {%8,%9}, {%0,%1,%2,%3};\n"
        : "+f"(c[0]), "+f"(c[1]), "+f"(c[2]), "+f"(c[3])
        : "r"(a[0]), "r"(a[1]), "r"(a[2]), "r"(a[3]), "r"(b0), "r"(b1));
}

__global__ __launch_bounds__(256, 2) void gemm_kernel(float* __restrict__ out) {
    extern __shared__ char smem[];
    uint32_t sbase;
    asm("{ .reg .u64 t; cvta.to.shared.u64 t, %1; cvt.u32.u64 %0, t; }"
        : "=r"(sbase) : "l"(smem));
    const int tid  = threadIdx.x;
    const int wid  = tid >> 5;
    const int lane = tid & 31;

    // GROUP_M=16 schedule: 64 M-tiles x 32 N-tiles
    const int pid   = blockIdx.x;
    const int group = pid >> 9;                       // / (16*32)
    const int rem   = pid & 511;
    const int blockM = ((group << 4) + (rem & 15)) * BM;
    const int blockN = (rem >> 4) * BN;

    // ---- loader mapping: q = 16B chunk (8 halfs), rows strided by 32 ----
    const int q  = tid & 7;
    const int r0 = tid >> 3;                          // 0..31
    const __half* gA = g_Xh + (size_t)(blockM + r0) * K_IN + q * 8;
    const __half* gB = g_Wh + (size_t)(blockN + r0) * K_IN + q * 8;
    const uint32_t soA = r0 * 128 + ((q ^ (r0 & 7)) << 4);
    const uint32_t soB = A_BYTES + soA;

    // ---- fragment geometry ----
    const int mBase = (wid & 1) * 64;                 // 2 M-warps
    const int nBase = (wid >> 1) * 32;                // 4 N-warps x 32
    const uint32_t rl = lane & 7;
    const uint32_t aKbAdd = (lane >> 4) & 1;
    const uint32_t bKbAdd = (lane >> 3) & 1;
    uint32_t aRowOff[4], bRowOff[2];
    #pragma unroll
    for (int i = 0; i < 4; i++)
        aRowOff[i] = (mBase + i * 16 + (lane & 7) + 8 * ((lane >> 3) & 1)) * 128;
    #pragma unroll
    for (int j2 = 0; j2 < 2; j2++)
        bRowOff[j2] = A_BYTES + (nBase + j2 * 16 + (lane & 7) + 8 * ((lane >> 4) & 1)) * 128;

    float acc[4][4][4];
    #pragma unroll
    for (int i = 0; i < 4; i++)
        #pragma unroll
        for (int j = 0; j < 4; j++)
            #pragma unroll
            for (int r = 0; r < 4; r++) acc[i][j][r] = 0.f;

    const int KT = K_IN / BK;                          // 64

    // prologue: stages 0,1
    #pragma unroll
    for (int t = 0; t < 2; t++) {
        uint32_t base = sbase + t * STG_BYTES;
        #pragma unroll
        for (int i = 0; i < 4; i++) {
            cpa16(base + soA + i * 4096, gA + (size_t)t * BK + (size_t)i * 32 * K_IN);
            cpa16(base + soB + i * 4096, gB + (size_t)t * BK + (size_t)i * 32 * K_IN);
        }
        asm volatile("cp.async.commit_group;");
    }

    int sCur = 0, sNxt = 2;                            // buf indices mod 3
    for (int t = 0; t < KT; t++) {
        asm volatile("cp.async.wait_group 1;");
        __syncthreads();

        if (t + 2 < KT) {
            uint32_t base = sbase + sNxt * STG_BYTES;
            const __half* ga = gA + (size_t)(t + 2) * BK;
            const __half* gb = gB + (size_t)(t + 2) * BK;
            #pragma unroll
            for (int i = 0; i < 4; i++) {
                cpa16(base + soA + i * 4096, ga + (size_t)i * 32 * K_IN);
                cpa16(base + soB + i * 4096, gb + (size_t)i * 32 * K_IN);
            }
        }
        asm volatile("cp.async.commit_group;");

        const uint32_t stage = sbase + sCur * STG_BYTES;
        #pragma unroll
        for (int c = 0; c < 4; c++) {                  // 4 x k16 = BK
            const uint32_t aXor = ((2 * c + aKbAdd) ^ rl) << 4;
            const uint32_t bXor = ((2 * c + bKbAdd) ^ rl) << 4;
            uint32_t af[4][4], bq[2][4];
            #pragma unroll
            for (int i = 0; i < 4; i++) ldsm4(af[i], stage + aRowOff[i] + aXor);
            #pragma unroll
            for (int j2 = 0; j2 < 2; j2++) ldsm4(bq[j2], stage + bRowOff[j2] + bXor);
            #pragma unroll
            for (int i = 0; i < 4; i++)
                #pragma unroll
                for (int j2 = 0; j2 < 2; j2++) {
                    mma16(acc[i][2 * j2],     af[i], bq[j2][0], bq[j2][1]);
                    mma16(acc[i][2 * j2 + 1], af[i], bq[j2][2], bq[j2][3]);
                }
        }
        sCur = sCur == 2 ? 0 : sCur + 1;
        sNxt = sNxt == 2 ? 0 : sNxt + 1;
    }

    // ---- epilogue: bias add + fp32 stores ----
    const int ly = lane >> 2, lx = lane & 3;
    float2 bias2[4];
    #pragma unroll
    for (int j = 0; j < 4; j++)
        bias2[j] = *(const float2*)&g_bias[blockN + nBase + j * 8 + lx * 2];
    #pragma unroll
    for (int i = 0; i < 4; i++) {
        const int row0 = blockM + mBase + i * 16 + ly;
        #pragma unroll
        for (int j = 0; j < 4; j++) {
            const int col = blockN + nBase + j * 8 + lx * 2;
            float2 v0 = make_float2(acc[i][j][0] + bias2[j].x, acc[i][j][1] + bias2[j].y);
            float2 v1 = make_float2(acc[i][j][2] + bias2[j].x, acc[i][j][3] + bias2[j].y);
            *(float2*)&out[(size_t)row0 * N_OUT + col] = v0;
            *(float2*)&out[(size_t)(row0 + 8) * N_OUT + col] = v1;
        }
    }
}

// ---------------------------------------------------------------------------
extern "C" void kernel_launch(void* const* d_in, const int* in_sizes, int n_in,
                              void* d_out, int out_size) {
    const float* x   = (const float*)d_in[0];
    const float* pls = (const float*)d_in[1];
    const float* qmu = (const float*)d_in[2];
    const float* qls = (const float*)d_in[3];
    const float* pmu = (const float*)d_in[4];
    const float* eps = (const float*)d_in[5];
    float* out = (float*)d_out;

    prep_fused<<<PREP_GRID, 256>>>(qmu, qls, pmu, eps, pls, x);

    cudaFuncSetAttribute(gemm_kernel, cudaFuncAttributeMaxDynamicSharedMemorySize, SMEM_TOTAL);
    gemm_kernel<<<(M_BATCH / BM) * (N_OUT / BN), 256, SMEM_TOTAL>>>(out);

    // KL reduce off the prep->gemm critical path (disjoint output region)
    kl_reduce_kernel<<<1, 256>>>(out, (long long)out_size - 1);
}

// round 12
// speedup vs baseline: 1.0505x; 1.0186x over previous
#include <cuda_runtime.h>
#include <cuda_fp16.h>
#include <cstdint>

#define M_BATCH 8192
#define N_OUT   4096
#define K_IN    4096

// Scratch (device globals: allocation-free per harness rules)
__device__ __half g_Wh[(size_t)N_OUT * K_IN];    // fp16 sampled weights (n,k)
__device__ __half g_Xh[(size_t)M_BATCH * K_IN];  // fp16 copy of x
__device__ float  g_bias[N_OUT];                 // sampled bias column
__device__ float  g_klpart[16640];               // per-block KL partials

#define NT4      4195328                          // (4096*4097)/4 float4s
#define WBLK     16388                            // ceil(NT4/256)
#define XBLK     16384                            // (8192*4096/8)/256
#define PREP_GRID (WBLK + XBLK)

// ---------------------------------------------------------------------------
// Fused prep: blocks [0,WBLK) sample W -> fp16 + bias + KL partials,
//             blocks [WBLK, WBLK+XBLK) convert X -> fp16. One pass, no loop.
// (round-9 version, measured 74 us @ 80% DRAM — frozen)
// ---------------------------------------------------------------------------
__global__ __launch_bounds__(256) void prep_fused(const float* __restrict__ qmu,
                                                  const float* __restrict__ qls,
                                                  const float* __restrict__ pmu,
                                                  const float* __restrict__ eps,
                                                  const float* __restrict__ plsp,
                                                  const float* __restrict__ X) {
    const int b = blockIdx.x;
    if (b < WBLK) {
        const float pls  = *plsp;
        const float inv2 = 0.5f * __expf(-2.0f * pls);
        float kl = 0.f;
        const int i4 = b * 256 + threadIdx.x;
        if (i4 < NT4) {
            float4 qm = ((const float4*)qmu)[i4];
            float4 ql = ((const float4*)qls)[i4];
            float4 pm = ((const float4*)pmu)[i4];
            float4 ep = ((const float4*)eps)[i4];
            #pragma unroll
            for (int j = 0; j < 4; j++) {
                float qmj = (&qm.x)[j], qlj = (&ql.x)[j];
                float pmj = (&pm.x)[j], epj = (&ep.x)[j];
                float qs = __expf(qlj);
                float w  = fmaf(qs, epj, qmj);
                int e = i4 * 4 + j;
                int n = e / 4097;
                int k = e - n * 4097;
                if (k < K_IN) g_Wh[(size_t)n * K_IN + k] = __float2half_rn(w);
                else          g_bias[n] = w;
                float d = pmj - qmj;
                kl += (pls - qlj) + fmaf(qs, qs, d * d) * inv2 - 0.5f;
            }
        }
        __shared__ float red[256];
        red[threadIdx.x] = kl;
        __syncthreads();
        #pragma unroll
        for (int s = 128; s > 0; s >>= 1) {
            if (threadIdx.x < s) red[threadIdx.x] += red[threadIdx.x + s];
            __syncthreads();
        }
        if (threadIdx.x == 0) g_klpart[b] = red[0];
    } else {
        const int i = (b - WBLK) * 256 + threadIdx.x;   // < 4,194,304
        float4 a = ((const float4*)X)[2 * i];
        float4 c = ((const float4*)X)[2 * i + 1];
        __half2 h[4];
        h[0] = __floats2half2_rn(a.x, a.y);
        h[1] = __floats2half2_rn(a.z, a.w);
        h[2] = __floats2half2_rn(c.x, c.y);
        h[3] = __floats2half2_rn(c.z, c.w);
        ((uint4*)g_Xh)[i] = *(uint4*)h;
    }
}

__global__ void kl_reduce_kernel(float* __restrict__ out, long long idx) {
    float local = 0.f;
    for (int i = threadIdx.x; i < WBLK; i += 256) local += g_klpart[i];
    __shared__ float red[256];
    red[threadIdx.x] = local;
    __syncthreads();
    #pragma unroll
    for (int s = 128; s > 0; s >>= 1) {
        if (threadIdx.x < s) red[threadIdx.x] += red[threadIdx.x + s];
        __syncthreads();
    }
    if (threadIdx.x == 0) out[idx] = red[0];
}

// ---------------------------------------------------------------------------
// fp16 mma.sync GEMM: out[m][n] = sum_k X[m][k]*W[n][k] + bias[n]
// CTA 128x128x64(halfs), 8 warps (2Mx4N), warp tile 64x32, 2 CTAs/SM.
// ldmatrix.x4.b16 on XOR-swizzled 128B rows, m16n8k16.f16, f32 acc.
// 3-stage cp.async pipeline. Round-6 body; t-loop unrolled x3 so the
// stage indices become compile-time constants and ptxas can software-
// pipeline across k-tile boundaries.
// ---------------------------------------------------------------------------
#define BM 128
#define BN 128
#define BK 64                          // halfs = 128 bytes per row
#define A_BYTES (BM * 128)             // 16384
#define STG_BYTES ((BM + BN) * 128)    // 32768
#define SMEM_TOTAL (3 * STG_BYTES)

__device__ __forceinline__ void cpa16(uint32_t daddr, const void* src) {
    asm volatile("cp.async.cg.shared.global [%0], [%1], 16;" :: "r"(daddr), "l"(src));
}

__device__ __forceinline__ void ldsm4(uint32_t* r, uint32_t addr) {
    asm volatile("ldmatrix.sync.aligned.m8n8.x4.shared.b16 {%0,%1,%2,%3}, [%4];"
                 : "=r"(r[0]), "=r"(r[1]), "=r"(r[2]), "=r"(r[3]) : "r"(addr));
}

__device__ __forceinline__ void mma16(float* c, const uint32_t* a, uint32_t b0, uint32_t b1) {
    asm volatile(
        "mma.sync.aligned.m16n8k16.row.col.f32.f16.f16.f32 "
        "{%0,%1,%2,%3}, {%4,%5,%6,%7}, {%8,%9}, {%0,%1,%2,%3};\n"
        : "+f"(c[0]), "+f"(c[1]), "+f"(c[2]), "+f"(c[3])
        : "r"(a[0]), "r"(a[1]), "r"(a[2]), "r"(a[3]), "r"(b0), "r"(b1));
}

__global__ __launch_bounds__(256, 2) void gemm_kernel(float* __restrict__ out) {
    extern __shared__ char smem[];
    uint32_t sbase;
    asm("{ .reg .u64 t; cvta.to.shared.u64 t, %1; cvt.u32.u64 %0, t; }"
        : "=r"(sbase) : "l"(smem));
    const int tid  = threadIdx.x;
    const int wid  = tid >> 5;
    const int lane = tid & 31;

    // GROUP_M=16 schedule: 64 M-tiles x 32 N-tiles
    const int pid   = blockIdx.x;
    const int group = pid >> 9;                       // / (16*32)
    const int rem   = pid & 511;
    const int blockM = ((group << 4) + (rem & 15)) * BM;
    const int blockN = (rem >> 4) * BN;

    // ---- loader mapping: q = 16B chunk (8 halfs), rows strided by 32 ----
    const int q  = tid & 7;
    const int r0 = tid >> 3;                          // 0..31
    const __half* gA = g_Xh + (size_t)(blockM + r0) * K_IN + q * 8;
    const __half* gB = g_Wh + (size_t)(blockN + r0) * K_IN + q * 8;
    const uint32_t soA = r0 * 128 + ((q ^ (r0 & 7)) << 4);
    const uint32_t soB = A_BYTES + soA;

    // ---- fragment geometry ----
    const int mBase = (wid & 1) * 64;                 // 2 M-warps
    const int nBase = (wid >> 1) * 32;                // 4 N-warps x 32
    const uint32_t rl = lane & 7;
    const uint32_t aKbAdd = (lane >> 4) & 1;
    const uint32_t bKbAdd = (lane >> 3) & 1;
    uint32_t aRowOff[4], bRowOff[2];
    #pragma unroll
    for (int i = 0; i < 4; i++)
        aRowOff[i] = (mBase + i * 16 + (lane & 7) + 8 * ((lane >> 3) & 1)) * 128;
    #pragma unroll
    for (int j2 = 0; j2 < 2; j2++)
        bRowOff[j2] = A_BYTES + (nBase + j2 * 16 + (lane & 7) + 8 * ((lane >> 4) & 1)) * 128;

    float acc[4][4][4];
    #pragma unroll
    for (int i = 0; i < 4; i++)
        #pragma unroll
        for (int j = 0; j < 4; j++)
            #pragma unroll
            for (int r = 0; r < 4; r++) acc[i][j][r] = 0.f;

    const int KT = K_IN / BK;                          // 64

    // prologue: stages 0,1
    #pragma unroll
    for (int t = 0; t < 2; t++) {
        uint32_t base = sbase + t * STG_BYTES;
        #pragma unroll
        for (int i = 0; i < 4; i++) {
            cpa16(base + soA + i * 4096, gA + (size_t)t * BK + (size_t)i * 32 * K_IN);
            cpa16(base + soB + i * 4096, gB + (size_t)t * BK + (size_t)i * 32 * K_IN);
        }
        asm volatile("cp.async.commit_group;");
    }

    #pragma unroll 3
    for (int t = 0; t < KT; t++) {
        asm volatile("cp.async.wait_group 1;");
        __syncthreads();

        if (t + 2 < KT) {
            uint32_t base = sbase + ((t + 2) % 3) * STG_BYTES;
            const __half* ga = gA + (size_t)(t + 2) * BK;
            const __half* gb = gB + (size_t)(t + 2) * BK;
            #pragma unroll
            for (int i = 0; i < 4; i++) {
                cpa16(base + soA + i * 4096, ga + (size_t)i * 32 * K_IN);
                cpa16(base + soB + i * 4096, gb + (size_t)i * 32 * K_IN);
            }
        }
        asm volatile("cp.async.commit_group;");

        const uint32_t stage = sbase + (t % 3) * STG_BYTES;
        #pragma unroll
        for (int c = 0; c < 4; c++) {                  // 4 x k16 = BK
            const uint32_t aXor = ((2 * c + aKbAdd) ^ rl) << 4;
            const uint32_t bXor = ((2 * c + bKbAdd) ^ rl) << 4;
            uint32_t af[4][4], bq[2][4];
            #pragma unroll
            for (int i = 0; i < 4; i++) ldsm4(af[i], stage + aRowOff[i] + aXor);
            #pragma unroll
            for (int j2 = 0; j2 < 2; j2++) ldsm4(bq[j2], stage + bRowOff[j2] + bXor);
            #pragma unroll
            for (int i = 0; i < 4; i++)
                #pragma unroll
                for (int j2 = 0; j2 < 2; j2++) {
                    mma16(acc[i][2 * j2],     af[i], bq[j2][0], bq[j2][1]);
                    mma16(acc[i][2 * j2 + 1], af[i], bq[j2][2], bq[j2][3]);
                }
        }
    }

    // ---- epilogue: bias add + fp32 stores ----
    const int ly = lane >> 2, lx = lane & 3;
    float2 bias2[4];
    #pragma unroll
    for (int j = 0; j < 4; j++)
        bias2[j] = *(const float2*)&g_bias[blockN + nBase + j * 8 + lx * 2];
    #pragma unroll
    for (int i = 0; i < 4; i++) {
        const int row0 = blockM + mBase + i * 16 + ly;
        #pragma unroll
        for (int j = 0; j < 4; j++) {
            const int col = blockN + nBase + j * 8 + lx * 2;
            float2 v0 = make_float2(acc[i][j][0] + bias2[j].x, acc[i][j][1] + bias2[j].y);
            float2 v1 = make_float2(acc[i][j][2] + bias2[j].x, acc[i][j][3] + bias2[j].y);
            *(float2*)&out[(size_t)row0 * N_OUT + col] = v0;
            *(float2*)&out[(size_t)(row0 + 8) * N_OUT + col] = v1;
        }
    }
}

// ---------------------------------------------------------------------------
extern "C" void kernel_launch(void* const* d_in, const int* in_sizes, int n_in,
                              void* d_out, int out_size) {
    const float* x   = (const float*)d_in[0];
    const float* pls = (const float*)d_in[1];
    const float* qmu = (const float*)d_in[2];
    const float* qls = (const float*)d_in[3];
    const float* pmu = (const float*)d_in[4];
    const float* eps = (const float*)d_in[5];
    float* out = (float*)d_out;

    prep_fused<<<PREP_GRID, 256>>>(qmu, qls, pmu, eps, pls, x);

    cudaFuncSetAttribute(gemm_kernel, cudaFuncAttributeMaxDynamicSharedMemorySize, SMEM_TOTAL);
    gemm_kernel<<<(M_BATCH / BM) * (N_OUT / BN), 256, SMEM_TOTAL>>>(out);

    // KL reduce off the prep->gemm critical path (disjoint output region)
    kl_reduce_kernel<<<1, 256>>>(out, (long long)out_size - 1);
}

// round 13
// speedup vs baseline: 1.1252x; 1.0711x over previous
#include <cuda_runtime.h>
#include <cuda_fp16.h>
#include <cstdint>

#define M_BATCH 8192
#define N_OUT   4096
#define K_IN    4096

// Scratch (device globals: allocation-free per harness rules)
__device__ __half g_Wh[(size_t)N_OUT * K_IN];    // fp16 sampled weights (n,k)
__device__ __half g_Xh[(size_t)M_BATCH * K_IN];  // fp16 copy of x
__device__ float  g_bias[N_OUT];                 // sampled bias column
__device__ float  g_klpart[16640];               // per-block KL partials

#define NT4      4195328                          // (4096*4097)/4 float4s
#define WBLK     16388                            // ceil(NT4/256)
#define XBLK     16384                            // (8192*4096/8)/256
#define PREP_GRID (WBLK + XBLK)

// ---------------------------------------------------------------------------
// Fused prep: blocks [0,WBLK) sample W -> fp16 + bias + KL partials,
//             blocks [WBLK, WBLK+XBLK) convert X -> fp16. One pass, no loop.
// (round-9 version, measured 74 us @ 80% DRAM — frozen)
// ---------------------------------------------------------------------------
__global__ __launch_bounds__(256) void prep_fused(const float* __restrict__ qmu,
                                                  const float* __restrict__ qls,
                                                  const float* __restrict__ pmu,
                                                  const float* __restrict__ eps,
                                                  const float* __restrict__ plsp,
                                                  const float* __restrict__ X) {
    const int b = blockIdx.x;
    if (b < WBLK) {
        const float pls  = *plsp;
        const float inv2 = 0.5f * __expf(-2.0f * pls);
        float kl = 0.f;
        const int i4 = b * 256 + threadIdx.x;
        if (i4 < NT4) {
            float4 qm = ((const float4*)qmu)[i4];
            float4 ql = ((const float4*)qls)[i4];
            float4 pm = ((const float4*)pmu)[i4];
            float4 ep = ((const float4*)eps)[i4];
            #pragma unroll
            for (int j = 0; j < 4; j++) {
                float qmj = (&qm.x)[j], qlj = (&ql.x)[j];
                float pmj = (&pm.x)[j], epj = (&ep.x)[j];
                float qs = __expf(qlj);
                float w  = fmaf(qs, epj, qmj);
                int e = i4 * 4 + j;
                int n = e / 4097;
                int k = e - n * 4097;
                if (k < K_IN) g_Wh[(size_t)n * K_IN + k] = __float2half_rn(w);
                else          g_bias[n] = w;
                float d = pmj - qmj;
                kl += (pls - qlj) + fmaf(qs, qs, d * d) * inv2 - 0.5f;
            }
        }
        __shared__ float red[256];
        red[threadIdx.x] = kl;
        __syncthreads();
        #pragma unroll
        for (int s = 128; s > 0; s >>= 1) {
            if (threadIdx.x < s) red[threadIdx.x] += red[threadIdx.x + s];
            __syncthreads();
        }
        if (threadIdx.x == 0) g_klpart[b] = red[0];
    } else {
        const int i = (b - WBLK) * 256 + threadIdx.x;   // < 4,194,304
        float4 a = ((const float4*)X)[2 * i];
        float4 c = ((const float4*)X)[2 * i + 1];
        __half2 h[4];
        h[0] = __floats2half2_rn(a.x, a.y);
        h[1] = __floats2half2_rn(a.z, a.w);
        h[2] = __floats2half2_rn(c.x, c.y);
        h[3] = __floats2half2_rn(c.z, c.w);
        ((uint4*)g_Xh)[i] = *(uint4*)h;
    }
}

__global__ void kl_reduce_kernel(float* __restrict__ out, long long idx) {
    float local = 0.f;
    for (int i = threadIdx.x; i < WBLK; i += 256) local += g_klpart[i];
    __shared__ float red[256];
    red[threadIdx.x] = local;
    __syncthreads();
    #pragma unroll
    for (int s = 128; s > 0; s >>= 1) {
        if (threadIdx.x < s) red[threadIdx.x] += red[threadIdx.x + s];
        __syncthreads();
    }
    if (threadIdx.x == 0) out[idx] = red[0];
}

// ---------------------------------------------------------------------------
// fp16 mma.sync GEMM: out[m][n] = sum_k X[m][k]*W[n][k] + bias[n]
// CTA 128x128x64(halfs), 8 warps (2Mx4N), warp tile 64x32, 2 CTAs/SM.
// ldmatrix.x4.b16 on XOR-swizzled 128B rows, m16n8k16.f16, f32 acc.
// 3-stage cp.async pipeline; t-loop unrolled x6 (stage indices constant,
// wider cross-tile software-pipelining window for ptxas).
// ---------------------------------------------------------------------------
#define BM 128
#define BN 128
#define BK 64                          // halfs = 128 bytes per row
#define A_BYTES (BM * 128)             // 16384
#define STG_BYTES ((BM + BN) * 128)    // 32768
#define SMEM_TOTAL (3 * STG_BYTES)

__device__ __forceinline__ void cpa16(uint32_t daddr, const void* src) {
    asm volatile("cp.async.cg.shared.global [%0], [%1], 16;" :: "r"(daddr), "l"(src));
}

__device__ __forceinline__ void ldsm4(uint32_t* r, uint32_t addr) {
    asm volatile("ldmatrix.sync.aligned.m8n8.x4.shared.b16 {%0,%1,%2,%3}, [%4];"
                 : "=r"(r[0]), "=r"(r[1]), "=r"(r[2]), "=r"(r[3]) : "r"(addr));
}

__device__ __forceinline__ void mma16(float* c, const uint32_t* a, uint32_t b0, uint32_t b1) {
    asm volatile(
        "mma.sync.aligned.m16n8k16.row.col.f32.f16.f16.f32 "
        "{%0,%1,%2,%3}, {%4,%5,%6,%7}, {%8,%9}, {%0,%1,%2,%3};\n"
        : "+f"(c[0]), "+f"(c[1]), "+f"(c[2]), "+f"(c[3])
        : "r"(a[0]), "r"(a[1]), "r"(a[2]), "r"(a[3]), "r"(b0), "r"(b1));
}

__global__ __launch_bounds__(256, 2) void gemm_kernel(float* __restrict__ out) {
    extern __shared__ char smem[];
    uint32_t sbase;
    asm("{ .reg .u64 t; cvta.to.shared.u64 t, %1; cvt.u32.u64 %0, t; }"
        : "=r"(sbase) : "l"(smem));
    const int tid  = threadIdx.x;
    const int wid  = tid >> 5;
    const int lane = tid & 31;

    // GROUP_M=16 schedule: 64 M-tiles x 32 N-tiles
    const int pid   = blockIdx.x;
    const int group = pid >> 9;                       // / (16*32)
    const int rem   = pid & 511;
    const int blockM = ((group << 4) + (rem & 15)) * BM;
    const int blockN = (rem >> 4) * BN;

    // ---- loader mapping: q = 16B chunk (8 halfs), rows strided by 32 ----
    const int q  = tid & 7;
    const int r0 = tid >> 3;                          // 0..31
    const __half* gA = g_Xh + (size_t)(blockM + r0) * K_IN + q * 8;
    const __half* gB = g_Wh + (size_t)(blockN + r0) * K_IN + q * 8;
    const uint32_t soA = r0 * 128 + ((q ^ (r0 & 7)) << 4);
    const uint32_t soB = A_BYTES + soA;

    // ---- fragment geometry ----
    const int mBase = (wid & 1) * 64;                 // 2 M-warps
    const int nBase = (wid >> 1) * 32;                // 4 N-warps x 32
    const uint32_t rl = lane & 7;
    const uint32_t aKbAdd = (lane >> 4) & 1;
    const uint32_t bKbAdd = (lane >> 3) & 1;
    uint32_t aRowOff[4], bRowOff[2];
    #pragma unroll
    for (int i = 0; i < 4; i++)
        aRowOff[i] = (mBase + i * 16 + (lane & 7) + 8 * ((lane >> 3) & 1)) * 128;
    #pragma unroll
    for (int j2 = 0; j2 < 2; j2++)
        bRowOff[j2] = A_BYTES + (nBase + j2 * 16 + (lane & 7) + 8 * ((lane >> 4) & 1)) * 128;

    float acc[4][4][4];
    #pragma unroll
    for (int i = 0; i < 4; i++)
        #pragma unroll
        for (int j = 0; j < 4; j++)
            #pragma unroll
            for (int r = 0; r < 4; r++) acc[i][j][r] = 0.f;

    const int KT = K_IN / BK;                          // 64

    // prologue: stages 0,1
    #pragma unroll
    for (int t = 0; t < 2; t++) {
        uint32_t base = sbase + t * STG_BYTES;
        #pragma unroll
        for (int i = 0; i < 4; i++) {
            cpa16(base + soA + i * 4096, gA + (size_t)t * BK + (size_t)i * 32 * K_IN);
            cpa16(base + soB + i * 4096, gB + (size_t)t * BK + (size_t)i * 32 * K_IN);
        }
        asm volatile("cp.async.commit_group;");
    }

    #pragma unroll 6
    for (int t = 0; t < KT; t++) {
        asm volatile("cp.async.wait_group 1;");
        __syncthreads();

        if (t + 2 < KT) {
            uint32_t base = sbase + ((t + 2) % 3) * STG_BYTES;
            const __half* ga = gA + (size_t)(t + 2) * BK;
            const __half* gb = gB + (size_t)(t + 2) * BK;
            #pragma unroll
            for (int i = 0; i < 4; i++) {
                cpa16(base + soA + i * 4096, ga + (size_t)i * 32 * K_IN);
                cpa16(base + soB + i * 4096, gb + (size_t)i * 32 * K_IN);
            }
        }
        asm volatile("cp.async.commit_group;");

        const uint32_t stage = sbase + (t % 3) * STG_BYTES;
        #pragma unroll
        for (int c = 0; c < 4; c++) {                  // 4 x k16 = BK
            const uint32_t aXor = ((2 * c + aKbAdd) ^ rl) << 4;
            const uint32_t bXor = ((2 * c + bKbAdd) ^ rl) << 4;
            uint32_t af[4][4], bq[2][4];
            #pragma unroll
            for (int i = 0; i < 4; i++) ldsm4(af[i], stage + aRowOff[i] + aXor);
            #pragma unroll
            for (int j2 = 0; j2 < 2; j2++) ldsm4(bq[j2], stage + bRowOff[j2] + bXor);
            #pragma unroll
            for (int i = 0; i < 4; i++)
                #pragma unroll
                for (int j2 = 0; j2 < 2; j2++) {
                    mma16(acc[i][2 * j2],     af[i], bq[j2][0], bq[j2][1]);
                    mma16(acc[i][2 * j2 + 1], af[i], bq[j2][2], bq[j2][3]);
                }
        }
    }

    // ---- epilogue: bias add + fp32 stores ----
    const int ly = lane >> 2, lx = lane & 3;
    float2 bias2[4];
    #pragma unroll
    for (int j = 0; j < 4; j++)
        bias2[j] = *(const float2*)&g_bias[blockN + nBase + j * 8 + lx * 2];
    #pragma unroll
    for (int i = 0; i < 4; i++) {
        const int row0 = blockM + mBase + i * 16 + ly;
        #pragma unroll
        for (int j = 0; j < 4; j++) {
            const int col = blockN + nBase + j * 8 + lx * 2;
            float2 v0 = make_float2(acc[i][j][0] + bias2[j].x, acc[i][j][1] + bias2[j].y);
            float2 v1 = make_float2(acc[i][j][2] + bias2[j].x, acc[i][j][3] + bias2[j].y);
            *(float2*)&out[(size_t)row0 * N_OUT + col] = v0;
            *(float2*)&out[(size_t)(row0 + 8) * N_OUT + col] = v1;
        }
    }
}

// ---------------------------------------------------------------------------
extern "C" void kernel_launch(void* const* d_in, const int* in_sizes, int n_in,
                              void* d_out, int out_size) {
    const float* x   = (const float*)d_in[0];
    const float* pls = (const float*)d_in[1];
    const float* qmu = (const float*)d_in[2];
    const float* qls = (const float*)d_in[3];
    const float* pmu = (const float*)d_in[4];
    const float* eps = (const float*)d_in[5];
    float* out = (float*)d_out;

    prep_fused<<<PREP_GRID, 256>>>(qmu, qls, pmu, eps, pls, x);

    cudaFuncSetAttribute(gemm_kernel, cudaFuncAttributeMaxDynamicSharedMemorySize, SMEM_TOTAL);
    gemm_kernel<<<(M_BATCH / BM) * (N_OUT / BN), 256, SMEM_TOTAL>>>(out);

    // KL reduce off the prep->gemm critical path (disjoint output region)
    kl_reduce_kernel<<<1, 256>>>(out, (long long)out_size - 1);
}

// round 14
// speedup vs baseline: 1.1435x; 1.0163x over previous
#include <cuda_runtime.h>
#include <cuda_fp16.h>
#include <cstdint>

#define M_BATCH 8192
#define N_OUT   4096
#define K_IN    4096

// Scratch (device globals: allocation-free per harness rules)
__device__ __half g_Wh[(size_t)N_OUT * K_IN];    // fp16 sampled weights (n,k)
__device__ __half g_Xh[(size_t)M_BATCH * K_IN];  // fp16 copy of x
__device__ float  g_bias[N_OUT];                 // sampled bias column
__device__ float  g_klpart[16640];               // per-block KL partials

#define NT4      4195328                          // (4096*4097)/4 float4s
#define WBLK     16388                            // ceil(NT4/256)
#define XBLK     16384                            // (8192*4096/8)/256
#define PREP_GRID (WBLK + XBLK)

// ---------------------------------------------------------------------------
// Fused prep: blocks [0,WBLK) sample W -> fp16 + bias + KL partials,
//             blocks [WBLK, WBLK+XBLK) convert X -> fp16. One pass, no loop.
// (round-9 version, measured 74 us @ 80% DRAM — frozen)
// ---------------------------------------------------------------------------
__global__ __launch_bounds__(256) void prep_fused(const float* __restrict__ qmu,
                                                  const float* __restrict__ qls,
                                                  const float* __restrict__ pmu,
                                                  const float* __restrict__ eps,
                                                  const float* __restrict__ plsp,
                                                  const float* __restrict__ X) {
    const int b = blockIdx.x;
    if (b < WBLK) {
        const float pls  = *plsp;
        const float inv2 = 0.5f * __expf(-2.0f * pls);
        float kl = 0.f;
        const int i4 = b * 256 + threadIdx.x;
        if (i4 < NT4) {
            float4 qm = ((const float4*)qmu)[i4];
            float4 ql = ((const float4*)qls)[i4];
            float4 pm = ((const float4*)pmu)[i4];
            float4 ep = ((const float4*)eps)[i4];
            #pragma unroll
            for (int j = 0; j < 4; j++) {
                float qmj = (&qm.x)[j], qlj = (&ql.x)[j];
                float pmj = (&pm.x)[j], epj = (&ep.x)[j];
                float qs = __expf(qlj);
                float w  = fmaf(qs, epj, qmj);
                int e = i4 * 4 + j;
                int n = e / 4097;
                int k = e - n * 4097;
                if (k < K_IN) g_Wh[(size_t)n * K_IN + k] = __float2half_rn(w);
                else          g_bias[n] = w;
                float d = pmj - qmj;
                kl += (pls - qlj) + fmaf(qs, qs, d * d) * inv2 - 0.5f;
            }
        }
        __shared__ float red[256];
        red[threadIdx.x] = kl;
        __syncthreads();
        #pragma unroll
        for (int s = 128; s > 0; s >>= 1) {
            if (threadIdx.x < s) red[threadIdx.x] += red[threadIdx.x + s];
            __syncthreads();
        }
        if (threadIdx.x == 0) g_klpart[b] = red[0];
    } else {
        const int i = (b - WBLK) * 256 + threadIdx.x;   // < 4,194,304
        float4 a = ((const float4*)X)[2 * i];
        float4 c = ((const float4*)X)[2 * i + 1];
        __half2 h[4];
        h[0] = __floats2half2_rn(a.x, a.y);
        h[1] = __floats2half2_rn(a.z, a.w);
        h[2] = __floats2half2_rn(c.x, c.y);
        h[3] = __floats2half2_rn(c.z, c.w);
        ((uint4*)g_Xh)[i] = *(uint4*)h;
    }
}

__global__ void kl_reduce_kernel(float* __restrict__ out, long long idx) {
    float local = 0.f;
    for (int i = threadIdx.x; i < WBLK; i += 256) local += g_klpart[i];
    __shared__ float red[256];
    red[threadIdx.x] = local;
    __syncthreads();
    #pragma unroll
    for (int s = 128; s > 0; s >>= 1) {
        if (threadIdx.x < s) red[threadIdx.x] += red[threadIdx.x + s];
        __syncthreads();
    }
    if (threadIdx.x == 0) out[idx] = red[0];
}

// ---------------------------------------------------------------------------
// fp16 mma.sync GEMM: out[m][n] = sum_k X[m][k]*W[n][k] + bias[n]
// CTA 128x128x64(halfs), 8 warps (2Mx4N), warp tile 64x32, 2 CTAs/SM.
// ldmatrix.x4.b16 on XOR-swizzled 128B rows, m16n8k16.f16, f32 acc.
// 3-stage cp.async pipeline; t-loop unrolled x12 (stage indices constant,
// wide cross-tile software-pipelining window for ptxas).
// ---------------------------------------------------------------------------
#define BM 128
#define BN 128
#define BK 64                          // halfs = 128 bytes per row
#define A_BYTES (BM * 128)             // 16384
#define STG_BYTES ((BM + BN) * 128)    // 32768
#define SMEM_TOTAL (3 * STG_BYTES)

__device__ __forceinline__ void cpa16(uint32_t daddr, const void* src) {
    asm volatile("cp.async.cg.shared.global [%0], [%1], 16;" :: "r"(daddr), "l"(src));
}

__device__ __forceinline__ void ldsm4(uint32_t* r, uint32_t addr) {
    asm volatile("ldmatrix.sync.aligned.m8n8.x4.shared.b16 {%0,%1,%2,%3}, [%4];"
                 : "=r"(r[0]), "=r"(r[1]), "=r"(r[2]), "=r"(r[3]) : "r"(addr));
}

__device__ __forceinline__ void mma16(float* c, const uint32_t* a, uint32_t b0, uint32_t b1) {
    asm volatile(
        "mma.sync.aligned.m16n8k16.row.col.f32.f16.f16.f32 "
        "{%0,%1,%2,%3}, {%4,%5,%6,%7}, {%8,%9}, {%0,%1,%2,%3};\n"
        : "+f"(c[0]), "+f"(c[1]), "+f"(c[2]), "+f"(c[3])
        : "r"(a[0]), "r"(a[1]), "r"(a[2]), "r"(a[3]), "r"(b0), "r"(b1));
}

__global__ __launch_bounds__(256, 2) void gemm_kernel(float* __restrict__ out) {
    extern __shared__ char smem[];
    uint32_t sbase;
    asm("{ .reg .u64 t; cvta.to.shared.u64 t, %1; cvt.u32.u64 %0, t; }"
        : "=r"(sbase) : "l"(smem));
    const int tid  = threadIdx.x;
    const int wid  = tid >> 5;
    const int lane = tid & 31;

    // GROUP_M=16 schedule: 64 M-tiles x 32 N-tiles
    const int pid   = blockIdx.x;
    const int group = pid >> 9;                       // / (16*32)
    const int rem   = pid & 511;
    const int blockM = ((group << 4) + (rem & 15)) * BM;
    const int blockN = (rem >> 4) * BN;

    // ---- loader mapping: q = 16B chunk (8 halfs), rows strided by 32 ----
    const int q  = tid & 7;
    const int r0 = tid >> 3;                          // 0..31
    const __half* gA = g_Xh + (size_t)(blockM + r0) * K_IN + q * 8;
    const __half* gB = g_Wh + (size_t)(blockN + r0) * K_IN + q * 8;
    const uint32_t soA = r0 * 128 + ((q ^ (r0 & 7)) << 4);
    const uint32_t soB = A_BYTES + soA;

    // ---- fragment geometry ----
    const int mBase = (wid & 1) * 64;                 // 2 M-warps
    const int nBase = (wid >> 1) * 32;                // 4 N-warps x 32
    const uint32_t rl = lane & 7;
    const uint32_t aKbAdd = (lane >> 4) & 1;
    const uint32_t bKbAdd = (lane >> 3) & 1;
    uint32_t aRowOff[4], bRowOff[2];
    #pragma unroll
    for (int i = 0; i < 4; i++)
        aRowOff[i] = (mBase + i * 16 + (lane & 7) + 8 * ((lane >> 3) & 1)) * 128;
    #pragma unroll
    for (int j2 = 0; j2 < 2; j2++)
        bRowOff[j2] = A_BYTES + (nBase + j2 * 16 + (lane & 7) + 8 * ((lane >> 4) & 1)) * 128;

    float acc[4][4][4];
    #pragma unroll
    for (int i = 0; i < 4; i++)
        #pragma unroll
        for (int j = 0; j < 4; j++)
            #pragma unroll
            for (int r = 0; r < 4; r++) acc[i][j][r] = 0.f;

    const int KT = K_IN / BK;                          // 64

    // prologue: stages 0,1
    #pragma unroll
    for (int t = 0; t < 2; t++) {
        uint32_t base = sbase + t * STG_BYTES;
        #pragma unroll
        for (int i = 0; i < 4; i++) {
            cpa16(base + soA + i * 4096, gA + (size_t)t * BK + (size_t)i * 32 * K_IN);
            cpa16(base + soB + i * 4096, gB + (size_t)t * BK + (size_t)i * 32 * K_IN);
        }
        asm volatile("cp.async.commit_group;");
    }

    #pragma unroll 12
    for (int t = 0; t < KT; t++) {
        asm volatile("cp.async.wait_group 1;");
        __syncthreads();

        if (t + 2 < KT) {
            uint32_t base = sbase + ((t + 2) % 3) * STG_BYTES;
            const __half* ga = gA + (size_t)(t + 2) * BK;
            const __half* gb = gB + (size_t)(t + 2) * BK;
            #pragma unroll
            for (int i = 0; i < 4; i++) {
                cpa16(base + soA + i * 4096, ga + (size_t)i * 32 * K_IN);
                cpa16(base + soB + i * 4096, gb + (size_t)i * 32 * K_IN);
            }
        }
        asm volatile("cp.async.commit_group;");

        const uint32_t stage = sbase + (t % 3) * STG_BYTES;
        #pragma unroll
        for (int c = 0; c < 4; c++) {                  // 4 x k16 = BK
            const uint32_t aXor = ((2 * c + aKbAdd) ^ rl) << 4;
            const uint32_t bXor = ((2 * c + bKbAdd) ^ rl) << 4;
            uint32_t af[4][4], bq[2][4];
            #pragma unroll
            for (int i = 0; i < 4; i++) ldsm4(af[i], stage + aRowOff[i] + aXor);
            #pragma unroll
            for (int j2 = 0; j2 < 2; j2++) ldsm4(bq[j2], stage + bRowOff[j2] + bXor);
            #pragma unroll
            for (int i = 0; i < 4; i++)
                #pragma unroll
                for (int j2 = 0; j2 < 2; j2++) {
                    mma16(acc[i][2 * j2],     af[i], bq[j2][0], bq[j2][1]);
                    mma16(acc[i][2 * j2 + 1], af[i], bq[j2][2], bq[j2][3]);
                }
        }
    }

    // ---- epilogue: bias add + fp32 stores ----
    const int ly = lane >> 2, lx = lane & 3;
    float2 bias2[4];
    #pragma unroll
    for (int j = 0; j < 4; j++)
        bias2[j] = *(const float2*)&g_bias[blockN + nBase + j * 8 + lx * 2];
    #pragma unroll
    for (int i = 0; i < 4; i++) {
        const int row0 = blockM + mBase + i * 16 + ly;
        #pragma unroll
        for (int j = 0; j < 4; j++) {
            const int col = blockN + nBase + j * 8 + lx * 2;
            float2 v0 = make_float2(acc[i][j][0] + bias2[j].x, acc[i][j][1] + bias2[j].y);
            float2 v1 = make_float2(acc[i][j][2] + bias2[j].x, acc[i][j][3] + bias2[j].y);
            *(float2*)&out[(size_t)row0 * N_OUT + col] = v0;
            *(float2*)&out[(size_t)(row0 + 8) * N_OUT + col] = v1;
        }
    }
}

// ---------------------------------------------------------------------------
extern "C" void kernel_launch(void* const* d_in, const int* in_sizes, int n_in,
                              void* d_out, int out_size) {
    const float* x   = (const float*)d_in[0];
    const float* pls = (const float*)d_in[1];
    const float* qmu = (const float*)d_in[2];
    const float* qls = (const float*)d_in[3];
    const float* pmu = (const float*)d_in[4];
    const float* eps = (const float*)d_in[5];
    float* out = (float*)d_out;

    prep_fused<<<PREP_GRID, 256>>>(qmu, qls, pmu, eps, pls, x);

    cudaFuncSetAttribute(gemm_kernel, cudaFuncAttributeMaxDynamicSharedMemorySize, SMEM_TOTAL);
    gemm_kernel<<<(M_BATCH / BM) * (N_OUT / BN), 256, SMEM_TOTAL>>>(out);

    // KL reduce off the prep->gemm critical path (disjoint output region)
    kl_reduce_kernel<<<1, 256>>>(out, (long long)out_size - 1);
}